// round 14
// baseline (speedup 1.0000x reference)
#include <cuda_runtime.h>

#define BB 8
#define CC 128
#define KK 19
#define NPIX 65536
#define BN (BB*NPIX)
#define NPBLK 512            // k_pred blocks = 64*8

// ---------------- scratch (device globals; no allocation) ----------------
__device__ float2 g_em[BN];            // sorted per 128-seg: (e, bits(idx<<8|widx<<5|cls))
__device__ float  g_Zp[NPBLK*KK];      // per-block partial sum of exp
__device__ float  g_Cp[NPBLK*KK];      // per-block partial pixel count
__device__ float  g_Xs[BB*KK*CC];      // unweighted segment sums of x
__device__ float  g_Xw[BB*KK*CC];      // exp-weighted segment sums of x
__device__ float  g_gmat[BB*KK*CC];    // g[b][k][d]
__device__ float  g_S1[BB*CC*KK];      // S1[b][d][k]

// ---- pass 1 (fused): argmax + e=exp(p) + counting-sort per 128-seg ----
// Z computed AFTER sorting from run-sums of the staged array (few low-conflict
// atomics) instead of per-pixel same-address atomics.
#define FPB 1024
__global__ void __launch_bounds__(256) k_pred(const float* __restrict__ preds){
    const int b  = blockIdx.y;
    const int bx = blockIdx.x;
    const int p0 = bx*FPB;
    const int t  = threadIdx.x;
    const int warp = t >> 5;
    const int lane = t & 31;
    const int bid  = b*64 + bx;

    // zero accumulator slices: 2*BB*KK*CC = 38912 = 512*76
    if (t < 76){
        int z = bid*76 + t;
        if (z < BB*KK*CC) g_Xs[z] = 0.f;
        else              g_Xw[z - BB*KK*CC] = 0.f;
    }

    const float4* r0 = (const float4*)(preds + (size_t)b*KK*NPIX + p0);
    float4 v = __ldg(&r0[t]);
    float bv[4] = {v.x, v.y, v.z, v.w};
    int   bk[4] = {0,0,0,0};
    #pragma unroll
    for (int k=1;k<KK;k++){
        float4 u = __ldg(&r0[t + k*(NPIX/4)]);
        if (u.x > bv[0]){ bv[0]=u.x; bk[0]=k; }
        if (u.y > bv[1]){ bv[1]=u.y; bk[1]=k; }
        if (u.z > bv[2]){ bv[2]=u.z; bk[2]=k; }
        if (u.w > bv[3]){ bv[3]=u.w; bk[3]=k; }
    }
    float ev[4];
    #pragma unroll
    for (int j=0;j<4;j++) ev[j] = expf(bv[j]);   // shift-invariant softmax

    __shared__ int    segCnt[8][20];
    __shared__ int    segStart[8][20];
    __shared__ float  sZ[KK];
    __shared__ float2 sEMst[FPB];                // staged sorted output (8 KB)
    if (t < 8*20) segCnt[t/20][t%20] = 0;
    if (t < KK)   sZ[t] = 0.f;
    __syncthreads();

    int rk[4];
    #pragma unroll
    for (int j=0;j<4;j++){
        unsigned mm = __match_any_sync(0xffffffffu, bk[j]);
        int ldr = __ffs(mm) - 1;
        int base = 0;
        if (lane == ldr) base = atomicAdd(&segCnt[warp][bk[j]], __popc(mm));
        base = __shfl_sync(0xffffffffu, base, ldr);
        rk[j] = base + __popc(mm & ((1u<<lane)-1u));
    }
    __syncthreads();
    if (t < 8){
        int s = 0;
        #pragma unroll
        for (int k=0;k<KK;k++){ segStart[t][k] = s; s += segCnt[t][k]; }
    }
    __syncthreads();

    const int i0 = 4*lane;
    #pragma unroll
    for (int j=0;j<4;j++){
        int pos = segStart[warp][bk[j]] + rk[j];
        int tag = ((pos >> 4) << 5) | bk[j];          // window id | class
        sEMst[warp*128 + pos] = make_float2(ev[j], __int_as_float(((i0+j)<<8) | tag));
    }
    __syncthreads();

    // coalesced global write: 1024 float2 = 512 float4, 2 per thread
    {
        const float4* src4 = (const float4*)sEMst;
        float4* dst4 = (float4*)(g_em + (size_t)b*NPIX + p0);
        dst4[t]       = src4[t];
        dst4[t + 256] = src4[t + 256];
    }

    // Z from sorted runs: 4 consecutive staged slots per thread (same 128-seg)
    {
        float2 q0 = sEMst[4*t+0], q1 = sEMst[4*t+1];
        float2 q2 = sEMst[4*t+2], q3 = sEMst[4*t+3];
        int c0 = __float_as_int(q0.y) & 31;
        int c1 = __float_as_int(q1.y) & 31;
        int c2 = __float_as_int(q2.y) & 31;
        int c3 = __float_as_int(q3.y) & 31;
        float s = q0.x; int c = c0;
        if (c1 == c) s += q1.x; else { atomicAdd(&sZ[c], s); c = c1; s = q1.x; }
        if (c2 == c) s += q2.x; else { atomicAdd(&sZ[c], s); c = c2; s = q2.x; }
        if (c3 == c) s += q3.x; else { atomicAdd(&sZ[c], s); c = c3; s = q3.x; }
        atomicAdd(&sZ[c], s);
    }
    __syncthreads();

    if (t < KK){
        g_Zp[bid*KK+t] = sZ[t];
        int c = 0;
        #pragma unroll
        for (int w=0;w<8;w++) c += segCnt[w][t];
        g_Cp[bid*KK+t] = (float)c;
    }
}

// ---------------- pass 2: heavy segment sums over x (R11, unchanged) ----------
#define PTILE 2048
#define PCH   128
#define NCHUNK (PTILE/PCH)                // 16
#define XSTRIDE 130                       // 520 B/row: 2-way LDS conflict max
#define XWORDS (32*XSTRIDE)
#define EMSTRIDE (PCH+2)                  // +2 sentinel slots (rotation reads p+2)
#define OFF_EM   (2*XWORDS*4)             // 33280 (16B aligned)
#define SMEM_BYTES (OFF_EM + 2*EMSTRIDE*8)  // 35360

__device__ __forceinline__ void cpasync8(unsigned saddr, const void* gaddr){
    asm volatile("cp.async.ca.shared.global [%0], [%1], 8;" :: "r"(saddr), "l"(gaddr));
}
__device__ __forceinline__ void cpcommit(){ asm volatile("cp.async.commit_group;"); }
template<int N> __device__ __forceinline__ void cpwait(){ asm volatile("cp.async.wait_group %0;" :: "n"(N)); }

__global__ void __launch_bounds__(256, 4) k_segsum(const float* __restrict__ x){
    __shared__ __align__(16) unsigned char smemRaw[SMEM_BYTES];
    float*  sXf = (float*)smemRaw;
    float2* sEM = (float2*)(smemRaw + OFF_EM);

    const int b    = blockIdx.z;
    const int c0   = blockIdx.y*32;
    const int pix0 = blockIdx.x*PTILE;
    const int t    = threadIdx.x;
    const int warp = t >> 5;
    const int lane = t & 31;

    const float* xb = x + (size_t)b*CC*NPIX + (size_t)c0*NPIX + pix0;
    unsigned sbase = (unsigned)__cvta_generic_to_shared(smemRaw);

    // sentinels tag 255 at slots 128,129 of each buffer (real tags <= 242)
    if (t < 4) sEM[(t>>1)*EMSTRIDE + PCH + (t&1)] = make_float2(0.f, __int_as_float(255));

    auto prefetch = [&](int ch, int buf){
        const float* gsrc = xb + ch*PCH;
        unsigned sx = sbase + (unsigned)buf*(XWORDS*4);
        #pragma unroll
        for (int j=0;j<8;j++){
            int u    = t + j*256;
            int row  = u >> 6;
            int unit = u & 63;
            cpasync8(sx + (unsigned)(row*XSTRIDE + unit*2)*4,
                     gsrc + (size_t)row*NPIX + unit*2);
        }
        if (t < 128){
            cpasync8(sbase + OFF_EM + (unsigned)buf*(EMSTRIDE*8) + (unsigned)t*8,
                     g_em + (size_t)b*NPIX + pix0 + ch*PCH + t);
        }
        cpcommit();
    };

    float accS[KK], accW[KK];
    #pragma unroll
    for (int k=0;k<KK;k++){ accS[k]=0.f; accW[k]=0.f; }

    prefetch(0, 0);
    for (int ch=0; ch<NCHUNK; ++ch){
        int buf = ch & 1;
        if (ch+1 < NCHUNK) prefetch(ch+1, buf^1);
        if (ch+1 < NCHUNK) cpwait<1>(); else cpwait<0>();
        __syncthreads();

        const float*  xrow = &sXf[buf*XWORDS + lane*XSTRIDE];
        const float2* ep   = &sEM[buf*EMSTRIDE];

        const int wend = warp*16 + 16;
        int p = warp*16;
        float2 cur = ep[p];
        float2 nxt = ep[p+1];
        while (p < wend){                         // once per RUN
            int tag = __float_as_int(cur.y) & 255;
            int k   = tag & 31;
            float ls = 0.f, lw = 0.f;
            bool cont;
            do {                                  // branch uses nxt loaded LAST iter
                float v = xrow[__float_as_int(cur.y) >> 8];
                ls += v;
                lw = fmaf(v, cur.x, lw);
                cont = ((__float_as_int(nxt.y) & 255) == tag);
                cur = nxt;
                ++p;
                nxt = ep[p+1];                    // lands a full body later
            } while (cont);
            switch(k){                            // once per run
            case 0:  accS[0] +=ls; accW[0] +=lw; break;
            case 1:  accS[1] +=ls; accW[1] +=lw; break;
            case 2:  accS[2] +=ls; accW[2] +=lw; break;
            case 3:  accS[3] +=ls; accW[3] +=lw; break;
            case 4:  accS[4] +=ls; accW[4] +=lw; break;
            case 5:  accS[5] +=ls; accW[5] +=lw; break;
            case 6:  accS[6] +=ls; accW[6] +=lw; break;
            case 7:  accS[7] +=ls; accW[7] +=lw; break;
            case 8:  accS[8] +=ls; accW[8] +=lw; break;
            case 9:  accS[9] +=ls; accW[9] +=lw; break;
            case 10: accS[10]+=ls; accW[10]+=lw; break;
            case 11: accS[11]+=ls; accW[11]+=lw; break;
            case 12: accS[12]+=ls; accW[12]+=lw; break;
            case 13: accS[13]+=ls; accW[13]+=lw; break;
            case 14: accS[14]+=ls; accW[14]+=lw; break;
            case 15: accS[15]+=ls; accW[15]+=lw; break;
            case 16: accS[16]+=ls; accW[16]+=lw; break;
            case 17: accS[17]+=ls; accW[17]+=lw; break;
            default: accS[18]+=ls; accW[18]+=lw; break;
            }
        }
        __syncthreads();
    }

    // ---- cross-warp smem tree reduce (x tile dead; reuse), then global RED ----
    float* red = (float*)smemRaw;   // [KK][8][32] = 19456 B < OFF_EM
    #pragma unroll
    for (int k=0;k<KK;k++) red[(k*8+warp)*32+lane] = accS[k];
    __syncthreads();
    for (int it=t; it<KK*32; it+=256){
        int k = it >> 5, ln = it & 31;
        float s = 0.f;
        #pragma unroll
        for (int w=0;w<8;w++) s += red[(k*8+w)*32+ln];
        atomicAdd(&g_Xs[(b*KK+k)*CC + c0 + ln], s);
    }
    __syncthreads();
    #pragma unroll
    for (int k=0;k<KK;k++) red[(k*8+warp)*32+lane] = accW[k];
    __syncthreads();
    for (int it=t; it<KK*32; it+=256){
        int k = it >> 5, ln = it & 31;
        float s = 0.f;
        #pragma unroll
        for (int w=0;w<8;w++) s += red[(k*8+w)*32+ln];
        atomicAdd(&g_Xw[(b*KK+k)*CC + c0 + ln], s);
    }
}

// ---------------- pass 3: tiny GEMMs, one block per (k,b), streamed weights ----
__global__ void __launch_bounds__(128) k_smallmm(
        const float* __restrict__ w1, const float* __restrict__ b1,
        const float* __restrict__ w2, const float* __restrict__ b2){
    const int k = blockIdx.x, b = blockIdx.y, t = threadIdx.x;  // t = d
    __shared__ float sXs[CC], sXw[CC];
    __shared__ float sZred[64], sCred[64];
    __shared__ float sZv, sCv;
    sXs[t] = g_Xs[(b*KK+k)*CC + t];
    sXw[t] = g_Xw[(b*KK+k)*CC + t];
    if (t < 64){
        sZred[t] = g_Zp[(b*64+t)*KK + k];
        sCred[t] = g_Cp[(b*64+t)*KK + k];
    }
    __syncthreads();
    if (t == 0){
        float z=0.f, c=0.f;
        #pragma unroll
        for (int i=0;i<64;i++){ z += sZred[i]; c += sCred[i]; }
        sZv = fmaxf(z, 1e-30f); sCv = c;
    }
    __syncthreads();

    const float4* w1r = (const float4*)(w1 + t*CC);
    const float4* w2r = (const float4*)(w2 + t*CC);
    float sa = 0.f, ga = 0.f;
    #pragma unroll 8
    for (int j=0;j<32;j++){
        float4 a = __ldg(&w1r[j]);
        float4 q = __ldg(&w2r[j]);
        sa = fmaf(a.x, sXs[4*j+0], sa); sa = fmaf(a.y, sXs[4*j+1], sa);
        sa = fmaf(a.z, sXs[4*j+2], sa); sa = fmaf(a.w, sXs[4*j+3], sa);
        ga = fmaf(q.x, sXw[4*j+0], ga); ga = fmaf(q.y, sXw[4*j+1], ga);
        ga = fmaf(q.z, sXw[4*j+2], ga); ga = fmaf(q.w, sXw[4*j+3], ga);
    }
    g_gmat[(b*KK+k)*CC + t] = ga/sZv + b2[t];
    g_S1[(b*CC+t)*KK + k]   = sa + b1[t]*sCv;
}

// ---------------- pass 4: gc = S1 @ g / sqrt(C), row softmax (R11 version) ----
__global__ void __launch_bounds__(128) k_out(float* __restrict__ out){
    int b = blockIdx.y, d1 = blockIdx.x, t = threadIdx.x;
    __shared__ float s1[KK];
    __shared__ float redm[4], reds[4];
    if (t < KK) s1[t] = g_S1[(b*CC+d1)*KK + t];
    __syncthreads();
    float acc = 0.f;
    const float* gb = g_gmat + b*KK*CC + t;
    #pragma unroll
    for (int k=0;k<KK;k++) acc = fmaf(s1[k], gb[k*CC], acc);
    acc *= 0.08838834764831845f;
    float m = acc;
    #pragma unroll
    for (int o=16;o;o>>=1) m = fmaxf(m, __shfl_xor_sync(0xffffffffu, m, o));
    if ((t&31)==0) redm[t>>5] = m;
    __syncthreads();
    m = fmaxf(fmaxf(redm[0],redm[1]), fmaxf(redm[2],redm[3]));
    float e = expf(acc - m);
    float s = e;
    #pragma unroll
    for (int o=16;o;o>>=1) s += __shfl_xor_sync(0xffffffffu, s, o);
    if ((t&31)==0) reds[t>>5] = s;
    __syncthreads();
    s = reds[0]+reds[1]+reds[2]+reds[3];
    out[((size_t)(b*CC+d1))*CC + t] = e/s;
}

// ---------------- launch ----------------
extern "C" void kernel_launch(void* const* d_in, const int* in_sizes, int n_in,
                              void* d_out, int out_size){
    const float* x     = (const float*)d_in[0];
    const float* preds = (const float*)d_in[1];
    const float* w1    = (const float*)d_in[2];
    const float* b1    = (const float*)d_in[3];
    const float* w2    = (const float*)d_in[4];
    const float* b2    = (const float*)d_in[5];
    float* out = (float*)d_out;

    k_pred   <<<dim3(NPIX/FPB, BB), 256>>>(preds);
    k_segsum <<<dim3(NPIX/PTILE, CC/32, BB), 256>>>(x);
    k_smallmm<<<dim3(KK, BB), 128>>>(w1, b1, w2, b2);
    k_out    <<<dim3(CC, BB), CC>>>(out);
    (void)in_sizes; (void)n_in; (void)out_size;
}

// round 15
// speedup vs baseline: 1.4434x; 1.4434x over previous
#include <cuda_runtime.h>

#define BB 8
#define CC 128
#define KK 19
#define NPIX 65536
#define BN (BB*NPIX)
#define NPBLK 512            // k_pred blocks = 64*8

// ---------------- scratch (device globals; no allocation) ----------------
__device__ float2 g_em[BN];            // sorted per 128-seg: (e, bits(idx<<8|widx<<5|cls))
__device__ float  g_Zp[NPBLK*KK];      // per-block partial sum of exp
__device__ float  g_Cp[NPBLK*KK];      // per-block partial pixel count
__device__ float  g_Xs[BB*KK*CC];      // unweighted segment sums of x
__device__ float  g_Xw[BB*KK*CC];      // exp-weighted segment sums of x
__device__ float  g_gmat[BB*KK*CC];    // g[b][k][d]
__device__ float  g_S1[BB*CC*KK];      // S1[b][d][k]

// ---- pass 1 (fused): argmax + e=exp(p) + counting-sort per 128-seg ----
#define FPB 1024
__global__ void __launch_bounds__(256) k_pred(const float* __restrict__ preds){
    const int b  = blockIdx.y;
    const int bx = blockIdx.x;
    const int p0 = bx*FPB;
    const int t  = threadIdx.x;
    const int warp = t >> 5;
    const int lane = t & 31;
    const int bid  = b*64 + bx;

    // zero accumulator slices: 2*BB*KK*CC = 38912 = 512*76
    if (t < 76){
        int z = bid*76 + t;
        if (z < BB*KK*CC) g_Xs[z] = 0.f;
        else              g_Xw[z - BB*KK*CC] = 0.f;
    }

    const float4* r0 = (const float4*)(preds + (size_t)b*KK*NPIX + p0);
    float4 v = __ldg(&r0[t]);
    float bv[4] = {v.x, v.y, v.z, v.w};
    int   bk[4] = {0,0,0,0};
    #pragma unroll
    for (int k=1;k<KK;k++){
        float4 u = __ldg(&r0[t + k*(NPIX/4)]);
        if (u.x > bv[0]){ bv[0]=u.x; bk[0]=k; }
        if (u.y > bv[1]){ bv[1]=u.y; bk[1]=k; }
        if (u.z > bv[2]){ bv[2]=u.z; bk[2]=k; }
        if (u.w > bv[3]){ bv[3]=u.w; bk[3]=k; }
    }
    float ev[4];
    #pragma unroll
    for (int j=0;j<4;j++) ev[j] = expf(bv[j]);   // shift-invariant softmax

    __shared__ int   segCnt[8][20];
    __shared__ int   segStart[8][20];
    __shared__ float sZ[KK];
    if (t < 8*20) segCnt[t/20][t%20] = 0;
    if (t < KK)   sZ[t] = 0.f;
    __syncthreads();

    int rk[4];
    #pragma unroll
    for (int j=0;j<4;j++){
        unsigned mm = __match_any_sync(0xffffffffu, bk[j]);
        int ldr = __ffs(mm) - 1;
        int base = 0;
        if (lane == ldr) base = atomicAdd(&segCnt[warp][bk[j]], __popc(mm));
        base = __shfl_sync(0xffffffffu, base, ldr);
        rk[j] = base + __popc(mm & ((1u<<lane)-1u));
        atomicAdd(&sZ[bk[j]], ev[j]);
    }
    __syncthreads();
    if (t < 8){
        int s = 0;
        #pragma unroll
        for (int k=0;k<KK;k++){ segStart[t][k] = s; s += segCnt[t][k]; }
    }
    __syncthreads();

    const int segbase = b*NPIX + p0 + warp*128;
    const int i0 = 4*lane;
    #pragma unroll
    for (int j=0;j<4;j++){
        int pos = segStart[warp][bk[j]] + rk[j];
        int tag = ((pos >> 4) << 5) | bk[j];          // window id | class
        g_em[segbase + pos] = make_float2(ev[j], __int_as_float(((i0+j)<<8) | tag));
    }
    if (t < KK){
        g_Zp[bid*KK+t] = sZ[t];
        int c = 0;
        #pragma unroll
        for (int w=0;w<8;w++) c += segCnt[w][t];
        g_Cp[bid*KK+t] = (float)c;
    }
}

// ---------------- pass 2: heavy segment sums over x ----------------
#define PTILE 2048
#define PCH   128
#define NCHUNK (PTILE/PCH)                // 16
#define XSTRIDE 130                       // 520 B/row: 2-way LDS conflict max
#define XWORDS (32*XSTRIDE)
#define EMSTRIDE (PCH+2)                  // +2 sentinel slots (rotation reads p+2)
#define OFF_EM   (2*XWORDS*4)             // 33280 (16B aligned)
#define SMEM_BYTES (OFF_EM + 2*EMSTRIDE*8)  // 35360

__device__ __forceinline__ void cpasync8(unsigned saddr, const void* gaddr){
    asm volatile("cp.async.ca.shared.global [%0], [%1], 8;" :: "r"(saddr), "l"(gaddr));
}
__device__ __forceinline__ void cpcommit(){ asm volatile("cp.async.commit_group;"); }
template<int N> __device__ __forceinline__ void cpwait(){ asm volatile("cp.async.wait_group %0;" :: "n"(N)); }

__global__ void __launch_bounds__(256, 4) k_segsum(const float* __restrict__ x){
    __shared__ __align__(16) unsigned char smemRaw[SMEM_BYTES];
    float*  sXf = (float*)smemRaw;
    float2* sEM = (float2*)(smemRaw + OFF_EM);

    const int b    = blockIdx.z;
    const int c0   = blockIdx.y*32;
    const int pix0 = blockIdx.x*PTILE;
    const int t    = threadIdx.x;
    const int warp = t >> 5;
    const int lane = t & 31;

    const float* xb = x + (size_t)b*CC*NPIX + (size_t)c0*NPIX + pix0;
    unsigned sbase = (unsigned)__cvta_generic_to_shared(smemRaw);

    // sentinels tag 255 at slots 128,129 of each buffer (real tags <= 242)
    if (t < 4) sEM[(t>>1)*EMSTRIDE + PCH + (t&1)] = make_float2(0.f, __int_as_float(255));

    auto prefetch = [&](int ch, int buf){
        const float* gsrc = xb + ch*PCH;
        unsigned sx = sbase + (unsigned)buf*(XWORDS*4);
        #pragma unroll
        for (int j=0;j<8;j++){
            int u    = t + j*256;
            int row  = u >> 6;
            int unit = u & 63;
            cpasync8(sx + (unsigned)(row*XSTRIDE + unit*2)*4,
                     gsrc + (size_t)row*NPIX + unit*2);
        }
        if (t < 128){
            cpasync8(sbase + OFF_EM + (unsigned)buf*(EMSTRIDE*8) + (unsigned)t*8,
                     g_em + (size_t)b*NPIX + pix0 + ch*PCH + t);
        }
        cpcommit();
    };

    float accS[KK], accW[KK];
    #pragma unroll
    for (int k=0;k<KK;k++){ accS[k]=0.f; accW[k]=0.f; }

    prefetch(0, 0);
    for (int ch=0; ch<NCHUNK; ++ch){
        int buf = ch & 1;
        if (ch+1 < NCHUNK) prefetch(ch+1, buf^1);
        if (ch+1 < NCHUNK) cpwait<1>(); else cpwait<0>();
        __syncthreads();

        const float*  xrow = &sXf[buf*XWORDS + lane*XSTRIDE];
        const float2* ep   = &sEM[buf*EMSTRIDE];

        const int wend = warp*16 + 16;
        int p = warp*16;
        float2 cur = ep[p];
        float2 nxt = ep[p+1];
        while (p < wend){                         // once per RUN
            int tag = __float_as_int(cur.y) & 255;
            int k   = tag & 31;
            float ls = 0.f, lw = 0.f;
            bool cont;
            do {                                  // branch uses nxt loaded LAST iter
                float v = xrow[__float_as_int(cur.y) >> 8];
                ls += v;
                lw = fmaf(v, cur.x, lw);
                cont = ((__float_as_int(nxt.y) & 255) == tag);
                cur = nxt;
                ++p;
                nxt = ep[p+1];                    // lands a full body later
            } while (cont);
            switch(k){                            // once per run
            case 0:  accS[0] +=ls; accW[0] +=lw; break;
            case 1:  accS[1] +=ls; accW[1] +=lw; break;
            case 2:  accS[2] +=ls; accW[2] +=lw; break;
            case 3:  accS[3] +=ls; accW[3] +=lw; break;
            case 4:  accS[4] +=ls; accW[4] +=lw; break;
            case 5:  accS[5] +=ls; accW[5] +=lw; break;
            case 6:  accS[6] +=ls; accW[6] +=lw; break;
            case 7:  accS[7] +=ls; accW[7] +=lw; break;
            case 8:  accS[8] +=ls; accW[8] +=lw; break;
            case 9:  accS[9] +=ls; accW[9] +=lw; break;
            case 10: accS[10]+=ls; accW[10]+=lw; break;
            case 11: accS[11]+=ls; accW[11]+=lw; break;
            case 12: accS[12]+=ls; accW[12]+=lw; break;
            case 13: accS[13]+=ls; accW[13]+=lw; break;
            case 14: accS[14]+=ls; accW[14]+=lw; break;
            case 15: accS[15]+=ls; accW[15]+=lw; break;
            case 16: accS[16]+=ls; accW[16]+=lw; break;
            case 17: accS[17]+=ls; accW[17]+=lw; break;
            default: accS[18]+=ls; accW[18]+=lw; break;
            }
        }
        __syncthreads();
    }

    // ---- cross-warp smem tree reduce (x tile dead; reuse), then global RED ----
    float* red = (float*)smemRaw;   // [KK][8][32] = 19456 B < OFF_EM
    #pragma unroll
    for (int k=0;k<KK;k++) red[(k*8+warp)*32+lane] = accS[k];
    __syncthreads();
    for (int it=t; it<KK*32; it+=256){
        int k = it >> 5, ln = it & 31;
        float s = 0.f;
        #pragma unroll
        for (int w=0;w<8;w++) s += red[(k*8+w)*32+ln];
        atomicAdd(&g_Xs[(b*KK+k)*CC + c0 + ln], s);
    }
    __syncthreads();
    #pragma unroll
    for (int k=0;k<KK;k++) red[(k*8+warp)*32+lane] = accW[k];
    __syncthreads();
    for (int it=t; it<KK*32; it+=256){
        int k = it >> 5, ln = it & 31;
        float s = 0.f;
        #pragma unroll
        for (int w=0;w<8;w++) s += red[(k*8+w)*32+ln];
        atomicAdd(&g_Xw[(b*KK+k)*CC + c0 + ln], s);
    }
}

// ---------------- pass 3: tiny GEMMs, one block per (k,b), streamed weights ----
__global__ void __launch_bounds__(128) k_smallmm(
        const float* __restrict__ w1, const float* __restrict__ b1,
        const float* __restrict__ w2, const float* __restrict__ b2){
    const int k = blockIdx.x, b = blockIdx.y, t = threadIdx.x;  // t = d
    __shared__ float sXs[CC], sXw[CC];
    __shared__ float sZred[64], sCred[64];
    __shared__ float sZv, sCv;
    sXs[t] = g_Xs[(b*KK+k)*CC + t];
    sXw[t] = g_Xw[(b*KK+k)*CC + t];
    if (t < 64){
        sZred[t] = g_Zp[(b*64+t)*KK + k];
        sCred[t] = g_Cp[(b*64+t)*KK + k];
    }
    __syncthreads();
    if (t == 0){
        float z=0.f, c=0.f;
        #pragma unroll
        for (int i=0;i<64;i++){ z += sZred[i]; c += sCred[i]; }
        sZv = fmaxf(z, 1e-30f); sCv = c;
    }
    __syncthreads();

    const float4* w1r = (const float4*)(w1 + t*CC);
    const float4* w2r = (const float4*)(w2 + t*CC);
    float sa = 0.f, ga = 0.f;
    #pragma unroll 8
    for (int j=0;j<32;j++){
        float4 a = __ldg(&w1r[j]);
        float4 q = __ldg(&w2r[j]);
        sa = fmaf(a.x, sXs[4*j+0], sa); sa = fmaf(a.y, sXs[4*j+1], sa);
        sa = fmaf(a.z, sXs[4*j+2], sa); sa = fmaf(a.w, sXs[4*j+3], sa);
        ga = fmaf(q.x, sXw[4*j+0], ga); ga = fmaf(q.y, sXw[4*j+1], ga);
        ga = fmaf(q.z, sXw[4*j+2], ga); ga = fmaf(q.w, sXw[4*j+3], ga);
    }
    g_gmat[(b*KK+k)*CC + t] = ga/sZv + b2[t];
    g_S1[(b*CC+t)*KK + k]   = sa + b1[t]*sCv;
}

// ---------------- pass 4: gc = S1 @ g / sqrt(C), row softmax ----------------
// 2 independent rows per block (R11 load pattern, half the blocks, no staging)
__global__ void __launch_bounds__(256) k_out(float* __restrict__ out){
    const int b  = blockIdx.y;
    const int t  = threadIdx.x;
    const int r  = t >> 7;          // row 0/1 within block
    const int d2 = t & 127;
    const int d1 = blockIdx.x*2 + r;

    __shared__ float s1[2][KK];
    __shared__ float redm[2][4], reds[2][4];
    if (d2 < KK) s1[r][d2] = g_S1[((size_t)b*CC + d1)*KK + d2];
    __syncthreads();

    float acc = 0.f;
    const float* gb = g_gmat + b*KK*CC + d2;
    #pragma unroll
    for (int k=0;k<KK;k++) acc = fmaf(s1[r][k], gb[k*CC], acc);
    acc *= 0.08838834764831845f;    // 128^-0.5

    const int wr = (t>>5) & 3;      // warp within row group
    float m = acc;
    #pragma unroll
    for (int o=16;o;o>>=1) m = fmaxf(m, __shfl_xor_sync(0xffffffffu, m, o));
    if ((t&31)==0) redm[r][wr] = m;
    __syncthreads();
    m = fmaxf(fmaxf(redm[r][0],redm[r][1]), fmaxf(redm[r][2],redm[r][3]));
    float e = expf(acc - m);
    float s = e;
    #pragma unroll
    for (int o=16;o;o>>=1) s += __shfl_xor_sync(0xffffffffu, s, o);
    if ((t&31)==0) reds[r][wr] = s;
    __syncthreads();
    s = reds[r][0]+reds[r][1]+reds[r][2]+reds[r][3];
    out[((size_t)(b*CC+d1))*CC + d2] = e/s;
}

// ---------------- launch ----------------
extern "C" void kernel_launch(void* const* d_in, const int* in_sizes, int n_in,
                              void* d_out, int out_size){
    const float* x     = (const float*)d_in[0];
    const float* preds = (const float*)d_in[1];
    const float* w1    = (const float*)d_in[2];
    const float* b1    = (const float*)d_in[3];
    const float* w2    = (const float*)d_in[4];
    const float* b2    = (const float*)d_in[5];
    float* out = (float*)d_out;

    k_pred   <<<dim3(NPIX/FPB, BB), 256>>>(preds);
    k_segsum <<<dim3(NPIX/PTILE, CC/32, BB), 256>>>(x);
    k_smallmm<<<dim3(KK, BB), 128>>>(w1, b1, w2, b2);
    k_out    <<<dim3(CC/2, BB), 256>>>(out);
    (void)in_sizes; (void)n_in; (void)out_size;
}

// round 16
// speedup vs baseline: 1.5112x; 1.0470x over previous
#include <cuda_runtime.h>

#define BB 8
#define CC 128
#define KK 19
#define NPIX 65536
#define BN (BB*NPIX)
#define NPBLK 512            // k_pred blocks = 64*8

// ---------------- scratch (device globals; no allocation) ----------------
__device__ float2 g_em[BN];            // sorted per 128-seg: (e, bits(idx<<8|widx<<5|cls))
__device__ float  g_Zp[NPBLK*KK];      // per-block partial sum of exp
__device__ float  g_Cp[NPBLK*KK];      // per-block partial pixel count
__device__ float  g_Xs[BB*KK*CC];      // unweighted segment sums of x
__device__ float  g_Xw[BB*KK*CC];      // exp-weighted segment sums of x
__device__ float  g_gmat[BB*KK*CC];    // g[b][k][d]
__device__ float  g_S1[BB*CC*KK];      // S1[b][d][k]

// ---- pass 1 (fused): argmax + e=exp(p) + counting-sort per 128-seg ----
#define FPB 1024
__global__ void __launch_bounds__(256) k_pred(const float* __restrict__ preds){
    const int b  = blockIdx.y;
    const int bx = blockIdx.x;
    const int p0 = bx*FPB;
    const int t  = threadIdx.x;
    const int warp = t >> 5;
    const int lane = t & 31;
    const int bid  = b*64 + bx;

    // zero accumulator slices: 2*BB*KK*CC = 38912 = 512*76
    if (t < 76){
        int z = bid*76 + t;
        if (z < BB*KK*CC) g_Xs[z] = 0.f;
        else              g_Xw[z - BB*KK*CC] = 0.f;
    }

    const float4* r0 = (const float4*)(preds + (size_t)b*KK*NPIX + p0);
    float4 v = __ldg(&r0[t]);
    float bv[4] = {v.x, v.y, v.z, v.w};
    int   bk[4] = {0,0,0,0};
    #pragma unroll
    for (int k=1;k<KK;k++){
        float4 u = __ldg(&r0[t + k*(NPIX/4)]);
        if (u.x > bv[0]){ bv[0]=u.x; bk[0]=k; }
        if (u.y > bv[1]){ bv[1]=u.y; bk[1]=k; }
        if (u.z > bv[2]){ bv[2]=u.z; bk[2]=k; }
        if (u.w > bv[3]){ bv[3]=u.w; bk[3]=k; }
    }
    float ev[4];
    #pragma unroll
    for (int j=0;j<4;j++) ev[j] = expf(bv[j]);   // shift-invariant softmax

    __shared__ int   segCnt[8][20];
    __shared__ int   segStart[8][20];
    __shared__ float sZ[KK];
    if (t < 8*20) segCnt[t/20][t%20] = 0;
    if (t < KK)   sZ[t] = 0.f;
    __syncthreads();

    int rk[4];
    #pragma unroll
    for (int j=0;j<4;j++){
        unsigned mm = __match_any_sync(0xffffffffu, bk[j]);
        int ldr = __ffs(mm) - 1;
        int base = 0;
        if (lane == ldr) base = atomicAdd(&segCnt[warp][bk[j]], __popc(mm));
        base = __shfl_sync(0xffffffffu, base, ldr);
        rk[j] = base + __popc(mm & ((1u<<lane)-1u));
        atomicAdd(&sZ[bk[j]], ev[j]);
    }
    __syncthreads();
    if (t < 8){
        int s = 0;
        #pragma unroll
        for (int k=0;k<KK;k++){ segStart[t][k] = s; s += segCnt[t][k]; }
    }
    __syncthreads();

    const int segbase = b*NPIX + p0 + warp*128;
    const int i0 = 4*lane;
    #pragma unroll
    for (int j=0;j<4;j++){
        int pos = segStart[warp][bk[j]] + rk[j];
        int tag = ((pos >> 4) << 5) | bk[j];          // window id | class
        g_em[segbase + pos] = make_float2(ev[j], __int_as_float(((i0+j)<<8) | tag));
    }
    if (t < KK){
        g_Zp[bid*KK+t] = sZ[t];
        int c = 0;
        #pragma unroll
        for (int w=0;w<8;w++) c += segCnt[w][t];
        g_Cp[bid*KK+t] = (float)c;
    }
}

// ---------------- pass 2: heavy segment sums over x ----------------
#define PTILE 2048
#define PCH   128
#define NCHUNK (PTILE/PCH)                // 16
#define XSTRIDE 130                       // 520 B/row: 2-way LDS conflict max
#define XWORDS (32*XSTRIDE)
#define EMSTRIDE (PCH+2)                  // +2 sentinel slots (rotation reads p+2)
#define OFF_EM   (2*XWORDS*4)             // 33280 (16B aligned)
#define SMEM_BYTES (OFF_EM + 2*EMSTRIDE*8)  // 35360

__device__ __forceinline__ void cpasync8(unsigned saddr, const void* gaddr){
    asm volatile("cp.async.ca.shared.global [%0], [%1], 8;" :: "r"(saddr), "l"(gaddr));
}
__device__ __forceinline__ void cpcommit(){ asm volatile("cp.async.commit_group;"); }
template<int N> __device__ __forceinline__ void cpwait(){ asm volatile("cp.async.wait_group %0;" :: "n"(N)); }

__global__ void __launch_bounds__(256, 4) k_segsum(const float* __restrict__ x){
    __shared__ __align__(16) unsigned char smemRaw[SMEM_BYTES];
    float*  sXf = (float*)smemRaw;
    float2* sEM = (float2*)(smemRaw + OFF_EM);

    const int b    = blockIdx.z;
    const int c0   = blockIdx.y*32;
    const int pix0 = blockIdx.x*PTILE;
    const int t    = threadIdx.x;
    const int warp = t >> 5;
    const int lane = t & 31;

    const float* xb = x + (size_t)b*CC*NPIX + (size_t)c0*NPIX + pix0;
    unsigned sbase = (unsigned)__cvta_generic_to_shared(smemRaw);

    // sentinels tag 255 at slots 128,129 of each buffer (real tags <= 242)
    if (t < 4) sEM[(t>>1)*EMSTRIDE + PCH + (t&1)] = make_float2(0.f, __int_as_float(255));

    auto prefetch = [&](int ch, int buf){
        const float* gsrc = xb + ch*PCH;
        unsigned sx = sbase + (unsigned)buf*(XWORDS*4);
        #pragma unroll
        for (int j=0;j<8;j++){
            int u    = t + j*256;
            int row  = u >> 6;
            int unit = u & 63;
            cpasync8(sx + (unsigned)(row*XSTRIDE + unit*2)*4,
                     gsrc + (size_t)row*NPIX + unit*2);
        }
        if (t < 128){
            cpasync8(sbase + OFF_EM + (unsigned)buf*(EMSTRIDE*8) + (unsigned)t*8,
                     g_em + (size_t)b*NPIX + pix0 + ch*PCH + t);
        }
        cpcommit();
    };

    float accS[KK], accW[KK];
    #pragma unroll
    for (int k=0;k<KK;k++){ accS[k]=0.f; accW[k]=0.f; }

    prefetch(0, 0);
    for (int ch=0; ch<NCHUNK; ++ch){
        int buf = ch & 1;
        if (ch+1 < NCHUNK) prefetch(ch+1, buf^1);
        if (ch+1 < NCHUNK) cpwait<1>(); else cpwait<0>();
        __syncthreads();

        const float*  xrow = &sXf[buf*XWORDS + lane*XSTRIDE];
        const float2* ep   = &sEM[buf*EMSTRIDE];

        const int wend = warp*16 + 16;
        int p = warp*16;
        float2 cur = ep[p];
        float2 nxt = ep[p+1];
        while (p < wend){                         // once per RUN
            int tag = __float_as_int(cur.y) & 255;
            int k   = tag & 31;
            float ls = 0.f, lw = 0.f;
            bool cont;
            do {                                  // branch uses nxt loaded LAST iter
                float v = xrow[__float_as_int(cur.y) >> 8];
                ls += v;
                lw = fmaf(v, cur.x, lw);
                cont = ((__float_as_int(nxt.y) & 255) == tag);
                cur = nxt;
                ++p;
                nxt = ep[p+1];                    // lands a full body later
            } while (cont);
            switch(k){                            // once per run
            case 0:  accS[0] +=ls; accW[0] +=lw; break;
            case 1:  accS[1] +=ls; accW[1] +=lw; break;
            case 2:  accS[2] +=ls; accW[2] +=lw; break;
            case 3:  accS[3] +=ls; accW[3] +=lw; break;
            case 4:  accS[4] +=ls; accW[4] +=lw; break;
            case 5:  accS[5] +=ls; accW[5] +=lw; break;
            case 6:  accS[6] +=ls; accW[6] +=lw; break;
            case 7:  accS[7] +=ls; accW[7] +=lw; break;
            case 8:  accS[8] +=ls; accW[8] +=lw; break;
            case 9:  accS[9] +=ls; accW[9] +=lw; break;
            case 10: accS[10]+=ls; accW[10]+=lw; break;
            case 11: accS[11]+=ls; accW[11]+=lw; break;
            case 12: accS[12]+=ls; accW[12]+=lw; break;
            case 13: accS[13]+=ls; accW[13]+=lw; break;
            case 14: accS[14]+=ls; accW[14]+=lw; break;
            case 15: accS[15]+=ls; accW[15]+=lw; break;
            case 16: accS[16]+=ls; accW[16]+=lw; break;
            case 17: accS[17]+=ls; accW[17]+=lw; break;
            default: accS[18]+=ls; accW[18]+=lw; break;
            }
        }
        __syncthreads();
    }

    // ---- cross-warp smem tree reduce (x tile dead; reuse), then global RED ----
    float* red = (float*)smemRaw;   // [KK][8][32] = 19456 B < OFF_EM
    #pragma unroll
    for (int k=0;k<KK;k++) red[(k*8+warp)*32+lane] = accS[k];
    __syncthreads();
    for (int it=t; it<KK*32; it+=256){
        int k = it >> 5, ln = it & 31;
        float s = 0.f;
        #pragma unroll
        for (int w=0;w<8;w++) s += red[(k*8+w)*32+ln];
        atomicAdd(&g_Xs[(b*KK+k)*CC + c0 + ln], s);
    }
    __syncthreads();
    #pragma unroll
    for (int k=0;k<KK;k++) red[(k*8+warp)*32+lane] = accW[k];
    __syncthreads();
    for (int it=t; it<KK*32; it+=256){
        int k = it >> 5, ln = it & 31;
        float s = 0.f;
        #pragma unroll
        for (int w=0;w<8;w++) s += red[(k*8+w)*32+ln];
        atomicAdd(&g_Xw[(b*KK+k)*CC + c0 + ln], s);
    }
}

// ---------------- pass 3: tiny GEMMs, one block per (k,b), streamed weights ----
__global__ void __launch_bounds__(128) k_smallmm(
        const float* __restrict__ w1, const float* __restrict__ b1,
        const float* __restrict__ w2, const float* __restrict__ b2){
    const int k = blockIdx.x, b = blockIdx.y, t = threadIdx.x;  // t = d
    __shared__ float sXs[CC], sXw[CC];
    __shared__ float sZred[64], sCred[64];
    __shared__ float sZv, sCv;
    sXs[t] = g_Xs[(b*KK+k)*CC + t];
    sXw[t] = g_Xw[(b*KK+k)*CC + t];
    if (t < 64){
        sZred[t] = g_Zp[(b*64+t)*KK + k];
        sCred[t] = g_Cp[(b*64+t)*KK + k];
    }
    __syncthreads();
    if (t == 0){
        float z=0.f, c=0.f;
        #pragma unroll
        for (int i=0;i<64;i++){ z += sZred[i]; c += sCred[i]; }
        sZv = fmaxf(z, 1e-30f); sCv = c;
    }
    __syncthreads();

    const float4* w1r = (const float4*)(w1 + t*CC);
    const float4* w2r = (const float4*)(w2 + t*CC);
    float sa = 0.f, ga = 0.f;
    #pragma unroll 8
    for (int j=0;j<32;j++){
        float4 a = __ldg(&w1r[j]);
        float4 q = __ldg(&w2r[j]);
        sa = fmaf(a.x, sXs[4*j+0], sa); sa = fmaf(a.y, sXs[4*j+1], sa);
        sa = fmaf(a.z, sXs[4*j+2], sa); sa = fmaf(a.w, sXs[4*j+3], sa);
        ga = fmaf(q.x, sXw[4*j+0], ga); ga = fmaf(q.y, sXw[4*j+1], ga);
        ga = fmaf(q.z, sXw[4*j+2], ga); ga = fmaf(q.w, sXw[4*j+3], ga);
    }
    g_gmat[(b*KK+k)*CC + t] = ga/sZv + b2[t];
    g_S1[(b*CC+t)*KK + k]   = sa + b1[t]*sCv;
}

// ---------------- pass 4: gc = S1 @ g / sqrt(C), row softmax ----------------
__global__ void __launch_bounds__(128) k_out(float* __restrict__ out){
    int b = blockIdx.y, d1 = blockIdx.x, t = threadIdx.x;
    __shared__ float s1[KK];
    __shared__ float redm[4], reds[4];
    if (t < KK) s1[t] = g_S1[(b*CC+d1)*KK + t];
    __syncthreads();
    float acc = 0.f;
    const float* gb = g_gmat + b*KK*CC + t;
    #pragma unroll
    for (int k=0;k<KK;k++) acc = fmaf(s1[k], gb[k*CC], acc);
    acc *= 0.08838834764831845f;
    float m = acc;
    #pragma unroll
    for (int o=16;o;o>>=1) m = fmaxf(m, __shfl_xor_sync(0xffffffffu, m, o));
    if ((t&31)==0) redm[t>>5] = m;
    __syncthreads();
    m = fmaxf(fmaxf(redm[0],redm[1]), fmaxf(redm[2],redm[3]));
    float e = expf(acc - m);
    float s = e;
    #pragma unroll
    for (int o=16;o;o>>=1) s += __shfl_xor_sync(0xffffffffu, s, o);
    if ((t&31)==0) reds[t>>5] = s;
    __syncthreads();
    s = reds[0]+reds[1]+reds[2]+reds[3];
    out[((size_t)(b*CC+d1))*CC + t] = e/s;
}

// ---------------- launch ----------------
extern "C" void kernel_launch(void* const* d_in, const int* in_sizes, int n_in,
                              void* d_out, int out_size){
    const float* x     = (const float*)d_in[0];
    const float* preds = (const float*)d_in[1];
    const float* w1    = (const float*)d_in[2];
    const float* b1    = (const float*)d_in[3];
    const float* w2    = (const float*)d_in[4];
    const float* b2    = (const float*)d_in[5];
    float* out = (float*)d_out;

    k_pred   <<<dim3(NPIX/FPB, BB), 256>>>(preds);
    k_segsum <<<dim3(NPIX/PTILE, CC/32, BB), 256>>>(x);
    k_smallmm<<<dim3(KK, BB), 128>>>(w1, b1, w2, b2);
    k_out    <<<dim3(CC, BB), CC>>>(out);
    (void)in_sizes; (void)n_in; (void)out_size;
}

// round 17
// speedup vs baseline: 1.5806x; 1.0459x over previous
#include <cuda_runtime.h>

#define BB 8
#define CC 128
#define KK 19
#define NPIX 65536
#define BN (BB*NPIX)
#define NPBLK 512            // k_pred blocks = 64*8

// ---------------- scratch (device globals; no allocation) ----------------
__device__ float2 g_em[BN];            // sorted per 128-seg: (e, bits(idx<<8|widx<<5|cls))
__device__ float  g_Zp[NPBLK*KK];      // per-block partial sum of exp
__device__ float  g_Cp[NPBLK*KK];      // per-block partial pixel count
__device__ float  g_Xs[BB*KK*CC];      // unweighted segment sums of x
__device__ float  g_Xw[BB*KK*CC];      // exp-weighted segment sums of x
__device__ float  g_gmat[BB*KK*CC];    // g[b][k][d]
__device__ float  g_S1[BB*CC*KK];      // S1[b][d][k]

// ---- pass 1 (fused): argmax + e=exp(p) + counting-sort per 128-seg ----
#define FPB 1024
__global__ void __launch_bounds__(256) k_pred(const float* __restrict__ preds){
    const int b  = blockIdx.y;
    const int bx = blockIdx.x;
    const int p0 = bx*FPB;
    const int t  = threadIdx.x;
    const int warp = t >> 5;
    const int lane = t & 31;
    const int bid  = b*64 + bx;

    // zero accumulator slices: 2*BB*KK*CC = 38912 = 512*76
    if (t < 76){
        int z = bid*76 + t;
        if (z < BB*KK*CC) g_Xs[z] = 0.f;
        else              g_Xw[z - BB*KK*CC] = 0.f;
    }

    const float4* r0 = (const float4*)(preds + (size_t)b*KK*NPIX + p0);
    float4 v = __ldg(&r0[t]);
    float bv[4] = {v.x, v.y, v.z, v.w};
    int   bk[4] = {0,0,0,0};
    #pragma unroll
    for (int k=1;k<KK;k++){
        float4 u = __ldg(&r0[t + k*(NPIX/4)]);
        if (u.x > bv[0]){ bv[0]=u.x; bk[0]=k; }
        if (u.y > bv[1]){ bv[1]=u.y; bk[1]=k; }
        if (u.z > bv[2]){ bv[2]=u.z; bk[2]=k; }
        if (u.w > bv[3]){ bv[3]=u.w; bk[3]=k; }
    }
    float ev[4];
    #pragma unroll
    for (int j=0;j<4;j++) ev[j] = expf(bv[j]);   // shift-invariant softmax

    __shared__ int   segCnt[8][20];
    __shared__ int   segStart[8][20];
    __shared__ float sZ[KK];
    if (t < 8*20) segCnt[t/20][t%20] = 0;
    if (t < KK)   sZ[t] = 0.f;
    __syncthreads();

    int rk[4];
    #pragma unroll
    for (int j=0;j<4;j++){
        unsigned mm = __match_any_sync(0xffffffffu, bk[j]);
        int ldr = __ffs(mm) - 1;
        int base = 0;
        if (lane == ldr) base = atomicAdd(&segCnt[warp][bk[j]], __popc(mm));
        base = __shfl_sync(0xffffffffu, base, ldr);
        rk[j] = base + __popc(mm & ((1u<<lane)-1u));
        atomicAdd(&sZ[bk[j]], ev[j]);
    }
    __syncthreads();
    if (t < 8){
        int s = 0;
        #pragma unroll
        for (int k=0;k<KK;k++){ segStart[t][k] = s; s += segCnt[t][k]; }
    }
    __syncthreads();

    const int segbase = b*NPIX + p0 + warp*128;
    const int i0 = 4*lane;
    #pragma unroll
    for (int j=0;j<4;j++){
        int pos = segStart[warp][bk[j]] + rk[j];
        int tag = ((pos >> 4) << 5) | bk[j];          // window id | class
        g_em[segbase + pos] = make_float2(ev[j], __int_as_float(((i0+j)<<8) | tag));
    }
    if (t < KK){
        g_Zp[bid*KK+t] = sZ[t];
        int c = 0;
        #pragma unroll
        for (int w=0;w<8;w++) c += segCnt[w][t];
        g_Cp[bid*KK+t] = (float)c;
    }
}

// ---------------- pass 2: heavy segment sums over x ----------------
#define PTILE 2048
#define PCH   128
#define NCHUNK (PTILE/PCH)                // 16
#define XSTRIDE 130                       // 520 B/row: 2-way LDS conflict max
#define XWORDS (32*XSTRIDE)
#define EMSTRIDE (PCH+2)                  // +2 sentinel slots (unroll reads p+3 <= 129)
#define OFF_EM   (2*XWORDS*4)             // 33280 (16B aligned)
#define SMEM_BYTES (OFF_EM + 2*EMSTRIDE*8)  // 35360

__device__ __forceinline__ void cpasync8(unsigned saddr, const void* gaddr){
    asm volatile("cp.async.ca.shared.global [%0], [%1], 8;" :: "r"(saddr), "l"(gaddr));
}
__device__ __forceinline__ void cpcommit(){ asm volatile("cp.async.commit_group;"); }
template<int N> __device__ __forceinline__ void cpwait(){ asm volatile("cp.async.wait_group %0;" :: "n"(N)); }

__global__ void __launch_bounds__(256, 4) k_segsum(const float* __restrict__ x){
    __shared__ __align__(16) unsigned char smemRaw[SMEM_BYTES];
    float*  sXf = (float*)smemRaw;
    float2* sEM = (float2*)(smemRaw + OFF_EM);

    const int b    = blockIdx.z;
    const int c0   = blockIdx.y*32;
    const int pix0 = blockIdx.x*PTILE;
    const int t    = threadIdx.x;
    const int warp = t >> 5;
    const int lane = t & 31;

    const float* xb = x + (size_t)b*CC*NPIX + (size_t)c0*NPIX + pix0;
    unsigned sbase = (unsigned)__cvta_generic_to_shared(smemRaw);

    // sentinels tag 255 at slots 128,129 of each buffer (real tags <= 242)
    if (t < 4) sEM[(t>>1)*EMSTRIDE + PCH + (t&1)] = make_float2(0.f, __int_as_float(255));

    auto prefetch = [&](int ch, int buf){
        const float* gsrc = xb + ch*PCH;
        unsigned sx = sbase + (unsigned)buf*(XWORDS*4);
        #pragma unroll
        for (int j=0;j<8;j++){
            int u    = t + j*256;
            int row  = u >> 6;
            int unit = u & 63;
            cpasync8(sx + (unsigned)(row*XSTRIDE + unit*2)*4,
                     gsrc + (size_t)row*NPIX + unit*2);
        }
        if (t < 128){
            cpasync8(sbase + OFF_EM + (unsigned)buf*(EMSTRIDE*8) + (unsigned)t*8,
                     g_em + (size_t)b*NPIX + pix0 + ch*PCH + t);
        }
        cpcommit();
    };

    float accS[KK], accW[KK];
    #pragma unroll
    for (int k=0;k<KK;k++){ accS[k]=0.f; accW[k]=0.f; }

    prefetch(0, 0);
    for (int ch=0; ch<NCHUNK; ++ch){
        int buf = ch & 1;
        if (ch+1 < NCHUNK) prefetch(ch+1, buf^1);
        if (ch+1 < NCHUNK) cpwait<1>(); else cpwait<0>();
        __syncthreads();

        const float*  xrow = &sXf[buf*XWORDS + lane*XSTRIDE];
        const float2* ep   = &sEM[buf*EMSTRIDE];

        const int wend = warp*16 + 16;
        int p = warp*16;
        float2 cur = ep[p];
        float2 nxt = ep[p+1];
        while (p < wend){                         // once per RUN
            int tag = __float_as_int(cur.y) & 255;
            int k   = tag & 31;
            float ls = 0.f, lw = 0.f;
            for (;;){                             // 2 pixels per iteration
                float v0 = xrow[__float_as_int(cur.y) >> 8];
                ls += v0;
                lw = fmaf(v0, cur.x, lw);
                bool c1 = ((__float_as_int(nxt.y) & 255) == tag);
                float2 la = ep[p+2];              // lookahead: <= slot 129 (sentinel)
                if (!c1){ p += 1; cur = nxt; nxt = la; break; }
                float v1 = xrow[__float_as_int(nxt.y) >> 8];
                ls += v1;
                lw = fmaf(v1, nxt.x, lw);
                float2 lb = ep[p+3];
                bool c2 = ((__float_as_int(la.y) & 255) == tag);
                p += 2; cur = la; nxt = lb;
                if (!c2) break;
            }
            switch(k){                            // once per run
            case 0:  accS[0] +=ls; accW[0] +=lw; break;
            case 1:  accS[1] +=ls; accW[1] +=lw; break;
            case 2:  accS[2] +=ls; accW[2] +=lw; break;
            case 3:  accS[3] +=ls; accW[3] +=lw; break;
            case 4:  accS[4] +=ls; accW[4] +=lw; break;
            case 5:  accS[5] +=ls; accW[5] +=lw; break;
            case 6:  accS[6] +=ls; accW[6] +=lw; break;
            case 7:  accS[7] +=ls; accW[7] +=lw; break;
            case 8:  accS[8] +=ls; accW[8] +=lw; break;
            case 9:  accS[9] +=ls; accW[9] +=lw; break;
            case 10: accS[10]+=ls; accW[10]+=lw; break;
            case 11: accS[11]+=ls; accW[11]+=lw; break;
            case 12: accS[12]+=ls; accW[12]+=lw; break;
            case 13: accS[13]+=ls; accW[13]+=lw; break;
            case 14: accS[14]+=ls; accW[14]+=lw; break;
            case 15: accS[15]+=ls; accW[15]+=lw; break;
            case 16: accS[16]+=ls; accW[16]+=lw; break;
            case 17: accS[17]+=ls; accW[17]+=lw; break;
            default: accS[18]+=ls; accW[18]+=lw; break;
            }
        }
        __syncthreads();
    }

    // ---- cross-warp smem tree reduce (x tile dead; reuse), then global RED ----
    float* red = (float*)smemRaw;   // [KK][8][32] = 19456 B < OFF_EM
    #pragma unroll
    for (int k=0;k<KK;k++) red[(k*8+warp)*32+lane] = accS[k];
    __syncthreads();
    for (int it=t; it<KK*32; it+=256){
        int k = it >> 5, ln = it & 31;
        float s = 0.f;
        #pragma unroll
        for (int w=0;w<8;w++) s += red[(k*8+w)*32+ln];
        atomicAdd(&g_Xs[(b*KK+k)*CC + c0 + ln], s);
    }
    __syncthreads();
    #pragma unroll
    for (int k=0;k<KK;k++) red[(k*8+warp)*32+lane] = accW[k];
    __syncthreads();
    for (int it=t; it<KK*32; it+=256){
        int k = it >> 5, ln = it & 31;
        float s = 0.f;
        #pragma unroll
        for (int w=0;w<8;w++) s += red[(k*8+w)*32+ln];
        atomicAdd(&g_Xw[(b*KK+k)*CC + c0 + ln], s);
    }
}

// ---------------- pass 3: tiny GEMMs, one block per (k,b), streamed weights ----
__global__ void __launch_bounds__(128) k_smallmm(
        const float* __restrict__ w1, const float* __restrict__ b1,
        const float* __restrict__ w2, const float* __restrict__ b2){
    const int k = blockIdx.x, b = blockIdx.y, t = threadIdx.x;  // t = d
    __shared__ float sXs[CC], sXw[CC];
    __shared__ float sZred[64], sCred[64];
    __shared__ float sZv, sCv;
    sXs[t] = g_Xs[(b*KK+k)*CC + t];
    sXw[t] = g_Xw[(b*KK+k)*CC + t];
    if (t < 64){
        sZred[t] = g_Zp[(b*64+t)*KK + k];
        sCred[t] = g_Cp[(b*64+t)*KK + k];
    }
    __syncthreads();
    if (t == 0){
        float z=0.f, c=0.f;
        #pragma unroll
        for (int i=0;i<64;i++){ z += sZred[i]; c += sCred[i]; }
        sZv = fmaxf(z, 1e-30f); sCv = c;
    }
    __syncthreads();

    const float4* w1r = (const float4*)(w1 + t*CC);
    const float4* w2r = (const float4*)(w2 + t*CC);
    float sa = 0.f, ga = 0.f;
    #pragma unroll 8
    for (int j=0;j<32;j++){
        float4 a = __ldg(&w1r[j]);
        float4 q = __ldg(&w2r[j]);
        sa = fmaf(a.x, sXs[4*j+0], sa); sa = fmaf(a.y, sXs[4*j+1], sa);
        sa = fmaf(a.z, sXs[4*j+2], sa); sa = fmaf(a.w, sXs[4*j+3], sa);
        ga = fmaf(q.x, sXw[4*j+0], ga); ga = fmaf(q.y, sXw[4*j+1], ga);
        ga = fmaf(q.z, sXw[4*j+2], ga); ga = fmaf(q.w, sXw[4*j+3], ga);
    }
    g_gmat[(b*KK+k)*CC + t] = ga/sZv + b2[t];
    g_S1[(b*CC+t)*KK + k]   = sa + b1[t]*sCv;
}

// ---------------- pass 4: gc = S1 @ g / sqrt(C), row softmax ----------------
__global__ void __launch_bounds__(128) k_out(float* __restrict__ out){
    int b = blockIdx.y, d1 = blockIdx.x, t = threadIdx.x;
    __shared__ float s1[KK];
    __shared__ float redm[4], reds[4];
    if (t < KK) s1[t] = g_S1[(b*CC+d1)*KK + t];
    __syncthreads();
    float acc = 0.f;
    const float* gb = g_gmat + b*KK*CC + t;
    #pragma unroll
    for (int k=0;k<KK;k++) acc = fmaf(s1[k], gb[k*CC], acc);
    acc *= 0.08838834764831845f;
    float m = acc;
    #pragma unroll
    for (int o=16;o;o>>=1) m = fmaxf(m, __shfl_xor_sync(0xffffffffu, m, o));
    if ((t&31)==0) redm[t>>5] = m;
    __syncthreads();
    m = fmaxf(fmaxf(redm[0],redm[1]), fmaxf(redm[2],redm[3]));
    float e = expf(acc - m);
    float s = e;
    #pragma unroll
    for (int o=16;o;o>>=1) s += __shfl_xor_sync(0xffffffffu, s, o);
    if ((t&31)==0) reds[t>>5] = s;
    __syncthreads();
    s = reds[0]+reds[1]+reds[2]+reds[3];
    out[((size_t)(b*CC+d1))*CC + t] = e/s;
}

// ---------------- launch ----------------
extern "C" void kernel_launch(void* const* d_in, const int* in_sizes, int n_in,
                              void* d_out, int out_size){
    const float* x     = (const float*)d_in[0];
    const float* preds = (const float*)d_in[1];
    const float* w1    = (const float*)d_in[2];
    const float* b1    = (const float*)d_in[3];
    const float* w2    = (const float*)d_in[4];
    const float* b2    = (const float*)d_in[5];
    float* out = (float*)d_out;

    k_pred   <<<dim3(NPIX/FPB, BB), 256>>>(preds);
    k_segsum <<<dim3(NPIX/PTILE, CC/32, BB), 256>>>(x);
    k_smallmm<<<dim3(KK, BB), 128>>>(w1, b1, w2, b2);
    k_out    <<<dim3(CC, BB), CC>>>(out);
    (void)in_sizes; (void)n_in; (void)out_size;
}